// round 13
// baseline (speedup 1.0000x reference)
#include <cuda_runtime.h>
#include <cuda_fp16.h>
#include <stdint.h>

#define BATCH 4
#define DIM 256
#define LL 2048
#define HEADS 8
#define DHEAD 64
#define HID 512
#define QKV_ROWS 1536
#define QPRESCALE 0.18033688011112042f

#define NX (BATCH * DIM * LL)
#define NQ (QKV_ROWS * DIM)
#define NO (DIM * HID)

__device__ __half g_qkv [(size_t)BATCH * QKV_ROWS * LL];
__device__ __half g_ao  [(size_t)BATCH * HID * LL];
__device__ __half g_xh  [NX];
__device__ __half g_wqk [NQ];
__device__ __half g_wo  [NO];

// ---------------------------------------------------------------------------
// PTX helpers
// ---------------------------------------------------------------------------
__device__ __forceinline__ uint32_t smem_u32(const void* p) {
    return (uint32_t)__cvta_generic_to_shared(p);
}
__device__ __forceinline__ void ldsm_x4(uint32_t r[4], uint32_t a) {
    asm volatile("ldmatrix.sync.aligned.m8n8.x4.shared.b16 {%0,%1,%2,%3}, [%4];"
        : "=r"(r[0]), "=r"(r[1]), "=r"(r[2]), "=r"(r[3]) : "r"(a));
}
__device__ __forceinline__ void ldsm_x4t(uint32_t r[4], uint32_t a) {
    asm volatile("ldmatrix.sync.aligned.m8n8.x4.trans.shared.b16 {%0,%1,%2,%3}, [%4];"
        : "=r"(r[0]), "=r"(r[1]), "=r"(r[2]), "=r"(r[3]) : "r"(a));
}
__device__ __forceinline__ void mma16816(float c[4], const uint32_t a[4],
                                         uint32_t b0, uint32_t b1) {
    asm volatile("mma.sync.aligned.m16n8k16.row.col.f32.f16.f16.f32 "
        "{%0,%1,%2,%3}, {%4,%5,%6,%7}, {%8,%9}, {%0,%1,%2,%3};"
        : "+f"(c[0]), "+f"(c[1]), "+f"(c[2]), "+f"(c[3])
        : "r"(a[0]), "r"(a[1]), "r"(a[2]), "r"(a[3]), "r"(b0), "r"(b1));
}
__device__ __forceinline__ void mma16816h(uint32_t c[2], const uint32_t a[4],
                                          uint32_t b0, uint32_t b1) {
    asm volatile("mma.sync.aligned.m16n8k16.row.col.f16.f16.f16.f16 "
        "{%0,%1}, {%2,%3,%4,%5}, {%6,%7}, {%0,%1};"
        : "+r"(c[0]), "+r"(c[1])
        : "r"(a[0]), "r"(a[1]), "r"(a[2]), "r"(a[3]), "r"(b0), "r"(b1));
}
__device__ __forceinline__ uint32_t packh2(float lo, float hi) {
    __half2 h = __floats2half2_rn(lo, hi);
    return *reinterpret_cast<uint32_t*>(&h);
}
__device__ __forceinline__ void cp16(void* s, const void* g) {
    asm volatile("cp.async.cg.shared.global [%0], [%1], 16;"
        :: "r"(smem_u32(s)), "l"(g));
}
__device__ __forceinline__ void cp_commit() {
    asm volatile("cp.async.commit_group;");
}
template <int N> __device__ __forceinline__ void cp_wait() {
    asm volatile("cp.async.wait_group %0;" :: "n"(N));
}
__device__ __forceinline__ uint32_t h2ex2(uint32_t x) {
    uint32_t r;
    asm("ex2.approx.f16x2 %0, %1;" : "=r"(r) : "r"(x));
    return r;
}
__device__ __forceinline__ __half2 u2h2(uint32_t x) {
    return *reinterpret_cast<__half2*>(&x);
}

// ---------------------------------------------------------------------------
__global__ void f2h_all(const float* __restrict__ x, const float* __restrict__ wq,
                        const float* __restrict__ wo,
                        __half* __restrict__ xh, __half* __restrict__ wqh,
                        __half* __restrict__ woh)
{
    int i = (blockIdx.x * blockDim.x + threadIdx.x) * 4;
    const float* s; __half* d; float sc = 1.0f; int j;
    if (i < NX)            { s = x;  d = xh;  j = i; }
    else if (i < NX + NQ)  { j = i - NX; s = wq; d = wqh;
                             if (j < HID * DIM) sc = QPRESCALE; }
    else if (i < NX+NQ+NO) { j = i - NX - NQ; s = wo; d = woh; }
    else return;
    float4 v = *(const float4*)(s + j);
    *(uint32_t*)(d + j)     = packh2(v.x * sc, v.y * sc);
    *(uint32_t*)(d + j + 2) = packh2(v.z * sc, v.w * sc);
}

// ---------------------------------------------------------------------------
// fp16 tensor-core GEMM (R9-proven, unchanged)
// ---------------------------------------------------------------------------
template <int BM, bool OUT_HALF, bool HAS_BIAS>
__global__ __launch_bounds__(256)
void hgemm_kernel(const __half* __restrict__ A, const __half* __restrict__ Bg,
                  void* __restrict__ Cg, const float* __restrict__ bias,
                  int M, int N, int K)
{
    constexpr int WN = (BM == 128) ? 2 : 4;
    constexpr int NT = 16 / WN;
    constexpr int NSPAN = 128 / WN;
    constexpr int A_SZ = BM * 72;
    constexpr int B_SZ = 64 * 136;

    const int b = blockIdx.z;
    const __half* Bm = Bg + (size_t)b * K * N;
    const int rowC0 = blockIdx.y * BM;
    const int colC0 = blockIdx.x * 128;

    extern __shared__ __half dsm[];
    __half* As = dsm;
    __half* Bs = dsm + 3 * A_SZ;

    const int tid = threadIdx.x, lane = tid & 31, warp = tid >> 5;
    const int g = lane >> 2, tg = lane & 3;
    const int wm = warp / WN, wn = warp % WN;

    const int lm_koff = ((lane >> 3) & 1) * 8 + (lane & 7);
    const int lm_noff = wn * NSPAN + ((lane >> 4) & 1) * 8;

    auto stage = [&](int buf, int k0) {
        __half* Ab = As + buf * A_SZ;
        #pragma unroll
        for (int it = 0; it < BM / 32; it++) {
            int c = tid + it * 256;
            int m = c >> 3, o8 = (c & 7) * 8;
            cp16(Ab + m * 72 + o8, A + (size_t)(rowC0 + m) * K + k0 + o8);
        }
        __half* Bb = Bs + buf * B_SZ;
        #pragma unroll
        for (int it = 0; it < 4; it++) {
            int c = tid + it * 256;
            int kk = c >> 4, n8 = (c & 15) * 8;
            cp16(Bb + kk * 136 + n8, Bm + (size_t)(k0 + kk) * N + colC0 + n8);
        }
    };

    float acc[2][NT][4] = {};
    const int ntiles = K >> 6;

    stage(0, 0);
    cp_commit();
    if (ntiles > 1) stage(1, 64);
    cp_commit();

    for (int kt = 0; kt < ntiles; kt++) {
        const int cur = kt % 3;
        cp_wait<1>();
        __syncthreads();

        const __half* Ab = As + cur * A_SZ;
        const uint32_t bsb = smem_u32(Bs + cur * B_SZ);
        #pragma unroll
        for (int kc = 0; kc < 4; kc++) {
            uint32_t af[2][4];
            #pragma unroll
            for (int mt = 0; mt < 2; mt++) {
                const __half* ap = Ab + (wm * 32 + mt * 16) * 72 + 16 * kc + 2 * tg;
                af[mt][0] = *(const uint32_t*)(ap + g * 72);
                af[mt][1] = *(const uint32_t*)(ap + (g + 8) * 72);
                af[mt][2] = *(const uint32_t*)(ap + g * 72 + 8);
                af[mt][3] = *(const uint32_t*)(ap + (g + 8) * 72 + 8);
            }
            uint32_t bf[NT][2];
            #pragma unroll
            for (int ntp = 0; ntp < NT / 2; ntp++) {
                uint32_t r[4];
                uint32_t a = bsb + 2 * ((16 * kc + lm_koff) * 136 +
                                        lm_noff + 16 * ntp);
                ldsm_x4t(r, a);
                bf[2*ntp][0] = r[0]; bf[2*ntp][1] = r[1];
                bf[2*ntp+1][0] = r[2]; bf[2*ntp+1][1] = r[3];
            }
            #pragma unroll
            for (int nt = 0; nt < NT; nt++)
                #pragma unroll
                for (int mt = 0; mt < 2; mt++)
                    mma16816(acc[mt][nt], af[mt], bf[nt][0], bf[nt][1]);
        }

        if (kt + 2 < ntiles) stage((kt + 2) % 3, (kt + 2) * 64);
        cp_commit();
    }

    #pragma unroll
    for (int mt = 0; mt < 2; mt++) {
        int m0 = rowC0 + wm * 32 + mt * 16 + g;
        #pragma unroll
        for (int nt = 0; nt < NT; nt++) {
            int n = colC0 + wn * NSPAN + nt * 8 + 2 * tg;
            float c0 = acc[mt][nt][0], c1 = acc[mt][nt][1];
            float c2 = acc[mt][nt][2], c3 = acc[mt][nt][3];
            if (OUT_HALF) {
                __half* Ch = (__half*)Cg + (size_t)b * M * N;
                *(uint32_t*)(Ch + (size_t)m0 * N + n)       = packh2(c0, c1);
                *(uint32_t*)(Ch + (size_t)(m0 + 8) * N + n) = packh2(c2, c3);
            } else {
                float* Cf = (float*)Cg + (size_t)b * M * N;
                float bv0 = HAS_BIAS ? bias[m0] : 0.0f;
                float bv1 = HAS_BIAS ? bias[m0 + 8] : 0.0f;
                *(float2*)(Cf + (size_t)m0 * N + n)       = make_float2(c0 + bv0, c1 + bv0);
                *(float2*)(Cf + (size_t)(m0 + 8) * N + n) = make_float2(c2 + bv1, c3 + bv1);
            }
        }
    }
}

// ---------------------------------------------------------------------------
// fp16 flash attention, 8 warps x 16 q-rows (256 threads), pipelined across
// KV tiles (S(t+1) interleaved with exp/PV(t)). Halved per-thread registers
// vs the 4-warp version -> 4 warps/SMSP resident (2 CTAs/SM) for latency
// hiding. K triple-buffered, V quad-buffered (V2,V3 alias dead Q staging).
// Sync: stage G(t+2) -> commit -> wait<1> -> barrier -> compute (race-free).
// ---------------------------------------------------------------------------
#define NTILES 32
#define KVB 9216                      // bytes per K or V buffer (64 x 72 halfs)
#define KS_OFF 18432                  // 3 K buffers
#define V01_OFF (18432 + 3 * KVB)     // 46080: V buffers 0,1
#define FL_BYTES (V01_OFF + 2 * KVB)  // 64512

__global__ __launch_bounds__(256)
void flash_kernel(const __half* __restrict__ qkv, __half* __restrict__ ao)
{
    const int b = blockIdx.z, h = blockIdx.y;
    const int i0 = blockIdx.x * 128;
    const int tid = threadIdx.x, lane = tid & 31, warp = tid >> 5;  // 0..7
    const int g = lane >> 2, tg = lane & 3;

    const __half* qg = qkv + ((size_t)b * QKV_ROWS + h * DHEAD) * LL;
    const __half* kg = qkv + ((size_t)b * QKV_ROWS + HID + h * DHEAD) * LL;
    const __half* vg = qkv + ((size_t)b * QKV_ROWS + 2 * HID + h * DHEAD) * LL;

    extern __shared__ __half sm[];
    __half* QV = sm;                          // Q staging / V2,V3 / O transpose
    const uint32_t sb = smem_u32(sm);

    auto stageK = [&](int buf, int j0) {
        __half* Kb = (__half*)((char*)sm + KS_OFF + buf * KVB);
        #pragma unroll
        for (int it = 0; it < 2; it++) {
            int idx = tid + it * 256;          // 512 chunks
            int d = idx >> 3, c8 = (idx & 7) * 8;
            cp16(Kb + d * 72 + c8, kg + (size_t)d * LL + j0 + c8);
        }
    };
    auto stageV = [&](int buf, int j0) {
        __half* Vb = (__half*)((char*)sm +
                     ((buf & 2) ? (buf & 1) * KVB : V01_OFF + (buf & 1) * KVB));
        #pragma unroll
        for (int it = 0; it < 2; it++) {
            int idx = tid + it * 256;
            int d = idx >> 3, c8 = (idx & 7) * 8;
            cp16(Vb + d * 72 + c8, vg + (size_t)d * LL + j0 + c8);
        }
    };

    // Prologue: G0, G1 in flight (V0,V1 to non-aliased region)
    stageK(0, 0);    stageV(0, 0);    cp_commit();
    stageK(1, 64);   stageV(1, 64);   cp_commit();

    // Stage Q (d, r) pitch 136; region is dead after fragments are built
    #pragma unroll
    for (int it = 0; it < 4; it++) {
        int idx = tid + it * 256;              // 1024 uint4
        int d = idx >> 4, q8 = (idx & 15) * 8;
        *(uint4*)(QV + d * 136 + q8) = *(const uint4*)(qg + (size_t)d * LL + i0 + q8);
    }
    __syncthreads();

    uint32_t qa[4][4];   // warp tile: 16 q-rows
    {
        int row = lane & 7;
        int c_off = ((lane >> 3) & 1) * 8;
        int d_off = ((lane >> 4) & 1) * 8;
        #pragma unroll
        for (int kc = 0; kc < 4; kc++) {
            uint32_t a = sb + 2 * ((16 * kc + d_off + row) * 136 +
                                   warp * 16 + c_off);
            ldsm_x4t(qa[kc], a);
        }
    }

    cp_wait<1>();        // own G0 done
    __syncthreads();     // all threads' G0 done; all qa ldsm complete

    const int lmr = lane & 7;
    const int lmo1 = ((lane >> 3) & 1) * 8;
    const int lmo2 = ((lane >> 4) & 1) * 8;

    float oc[8][4] = {};
    float lr[2] = {};
    uint32_t schA[8][2], schB[8][2];

    // S(0) from K buffer 0
    {
        #pragma unroll
        for (int jc = 0; jc < 8; jc++) { schA[jc][0] = 0; schA[jc][1] = 0; }
        const uint32_t kbb = sb + KS_OFF;
        #pragma unroll
        for (int kc = 0; kc < 4; kc++) {
            uint32_t kb[8][2];
            #pragma unroll
            for (int jp = 0; jp < 4; jp++) {
                uint32_t r[4];
                uint32_t a = kbb + 2 * ((16 * kc + lmo1 + lmr) * 72 + 16 * jp + lmo2);
                ldsm_x4t(r, a);
                kb[2*jp][0] = r[0]; kb[2*jp][1] = r[1];
                kb[2*jp+1][0] = r[2]; kb[2*jp+1][1] = r[3];
            }
            #pragma unroll
            for (int jc = 0; jc < 8; jc++)
                mma16816h(schA[jc], qa[kc], kb[jc][0], kb[jc][1]);
        }
    }

    // Body: consumes si = sch(t), produces so = sch(t+1); PV(t) interleaved
    auto body = [&](uint32_t (&si)[8][2], uint32_t (&so)[8][2], int t) {
        if (t + 2 < NTILES) { stageK((t + 2) % 3, (t + 2) * 64);
                              stageV((t + 2) & 3, (t + 2) * 64); }
        cp_commit();
        cp_wait<1>();        // own G(t+1) complete
        __syncthreads();     // everyone's G(t+1) complete; buffer reuse safe

        const bool doS = (t + 1 < NTILES);
        const uint32_t kbb = sb + KS_OFF + ((t + 1) % 3) * KVB;
        const uint32_t vbb = sb + ((t & 2) ? (t & 1) * KVB
                                           : V01_OFF + (t & 1) * KVB);
        if (doS) {
            #pragma unroll
            for (int jc = 0; jc < 8; jc++) { so[jc][0] = 0; so[jc][1] = 0; }
        }

        __half2 hl[2] = {__half2(0,0), __half2(0,0)};
        #pragma unroll
        for (int blk = 0; blk < 4; blk++) {
            // --- S(t+1), k-chunk blk ---
            if (doS) {
                uint32_t kb[8][2];
                #pragma unroll
                for (int jp = 0; jp < 4; jp++) {
                    uint32_t r[4];
                    uint32_t a = kbb + 2 * ((16 * blk + lmo1 + lmr) * 72 +
                                            16 * jp + lmo2);
                    ldsm_x4t(r, a);
                    kb[2*jp][0] = r[0]; kb[2*jp][1] = r[1];
                    kb[2*jp+1][0] = r[2]; kb[2*jp+1][1] = r[3];
                }
                #pragma unroll
                for (int jc = 0; jc < 8; jc++)
                    mma16816h(so[jc], qa[blk], kb[jc][0], kb[jc][1]);
            }
            // --- exp + PV(t), j-chunk blk ---
            uint32_t pa[4];
            pa[0] = h2ex2(si[2*blk][0]);
            pa[1] = h2ex2(si[2*blk][1]);
            pa[2] = h2ex2(si[2*blk+1][0]);
            pa[3] = h2ex2(si[2*blk+1][1]);
            hl[0] = __hadd2(hl[0], __hadd2(u2h2(pa[0]), u2h2(pa[2])));
            hl[1] = __hadd2(hl[1], __hadd2(u2h2(pa[1]), u2h2(pa[3])));
            #pragma unroll
            for (int dp = 0; dp < 4; dp++) {
                uint32_t r[4];
                uint32_t a = vbb + 2 * ((16 * dp + lmo2 + lmr) * 72 +
                                        16 * blk + lmo1);
                ldsm_x4(r, a);
                mma16816(oc[2*dp],   pa, r[0], r[1]);
                mma16816(oc[2*dp+1], pa, r[2], r[3]);
            }
        }
        float2 f0 = __half22float2(hl[0]);
        float2 f1 = __half22float2(hl[1]);
        lr[0] += f0.x + f0.y;
        lr[1] += f1.x + f1.y;
    };

    for (int jt = 0; jt < NTILES; jt += 2) {
        body(schA, schB, jt);
        body(schB, schA, jt + 1);
    }

    // Reduce row sums across the quad
    #pragma unroll
    for (int rr = 0; rr < 2; rr++) {
        lr[rr] += __shfl_xor_sync(~0u, lr[rr], 1);
        lr[rr] += __shfl_xor_sync(~0u, lr[rr], 2);
    }

    __syncthreads();   // all PV(31)/PV(30) ldsm done before QV reuse for O

    {
        float inv0 = 1.0f / lr[0];
        float inv1 = 1.0f / lr[1];
        int r_lo = warp * 16 + g, r_hi = r_lo + 8;
        #pragma unroll
        for (int dc = 0; dc < 8; dc++) {
            int d = dc * 8 + 2 * tg;
            QV[d * 136 + r_lo]       = __float2half(oc[dc][0] * inv0);
            QV[(d + 1) * 136 + r_lo] = __float2half(oc[dc][1] * inv0);
            QV[d * 136 + r_hi]       = __float2half(oc[dc][2] * inv1);
            QV[(d + 1) * 136 + r_hi] = __float2half(oc[dc][3] * inv1);
        }
    }
    __syncthreads();

    __half* aog = ao + ((size_t)b * HID + h * DHEAD) * LL;
    #pragma unroll
    for (int it = 0; it < 4; it++) {
        int idx = tid + it * 256;
        int d = idx >> 4, q8 = (idx & 15) * 8;
        *(uint4*)(aog + (size_t)d * LL + i0 + q8) = *(const uint4*)(QV + d * 136 + q8);
    }
}

// ---------------------------------------------------------------------------
extern "C" void kernel_launch(void* const* d_in, const int* in_sizes, int n_in,
                              void* d_out, int out_size)
{
    (void)in_sizes; (void)n_in; (void)out_size;
    const float* x     = (const float*)d_in[0];
    const float* w_qkv = (const float*)d_in[1];
    const float* w_out = (const float*)d_in[2];
    const float* b_out = (const float*)d_in[3];
    float* out = (float*)d_out;

    __half *qkv, *ao, *xh, *wqk, *wo;
    cudaGetSymbolAddress((void**)&qkv, g_qkv);
    cudaGetSymbolAddress((void**)&ao,  g_ao);
    cudaGetSymbolAddress((void**)&xh,  g_xh);
    cudaGetSymbolAddress((void**)&wqk, g_wqk);
    cudaGetSymbolAddress((void**)&wo,  g_wo);

    {
        int total4 = (NX + NQ + NO) / 4;
        f2h_all<<<(total4 + 255) / 256, 256>>>(x, w_qkv, w_out, xh, wqk, wo);
    }

    const int gm1_smem = 3 * (128 * 72 + 64 * 136) * 2;
    const int gm3_smem = 3 * (64 * 72 + 64 * 136) * 2;
    cudaFuncSetAttribute((const void*)hgemm_kernel<128, true, false>,
                         cudaFuncAttributeMaxDynamicSharedMemorySize, gm1_smem);
    cudaFuncSetAttribute((const void*)hgemm_kernel<64, false, true>,
                         cudaFuncAttributeMaxDynamicSharedMemorySize, gm3_smem);
    cudaFuncSetAttribute((const void*)flash_kernel,
                         cudaFuncAttributeMaxDynamicSharedMemorySize, FL_BYTES);

    dim3 g1(LL / 128, QKV_ROWS / 128, BATCH);
    hgemm_kernel<128, true, false><<<g1, 256, gm1_smem>>>(wqk, xh, qkv, nullptr,
                                                          QKV_ROWS, LL, DIM);

    dim3 g2(LL / 128, HEADS, BATCH);
    flash_kernel<<<g2, 256, FL_BYTES>>>(qkv, ao);

    dim3 g3(LL / 128, DIM / 64, BATCH);
    hgemm_kernel<64, false, true><<<g3, 256, gm3_smem>>>(wo, ao, out, b_out,
                                                         DIM, LL, HID);
}

// round 14
// speedup vs baseline: 1.1777x; 1.1777x over previous
#include <cuda_runtime.h>
#include <cuda_fp16.h>
#include <stdint.h>

#define BATCH 4
#define DIM 256
#define LL 2048
#define HEADS 8
#define DHEAD 64
#define HID 512
#define QKV_ROWS 1536
#define QPRESCALE 0.18033688011112042f

#define NX (BATCH * DIM * LL)
#define NQ (QKV_ROWS * DIM)
#define NO (DIM * HID)

__device__ __half g_qkv [(size_t)BATCH * QKV_ROWS * LL];
__device__ __half g_ao  [(size_t)BATCH * HID * LL];
__device__ __half g_xh  [NX];
__device__ __half g_wqk [NQ];
__device__ __half g_wo  [NO];

// ---------------------------------------------------------------------------
// PTX helpers
// ---------------------------------------------------------------------------
__device__ __forceinline__ uint32_t smem_u32(const void* p) {
    return (uint32_t)__cvta_generic_to_shared(p);
}
__device__ __forceinline__ void ldsm_x4(uint32_t r[4], uint32_t a) {
    asm volatile("ldmatrix.sync.aligned.m8n8.x4.shared.b16 {%0,%1,%2,%3}, [%4];"
        : "=r"(r[0]), "=r"(r[1]), "=r"(r[2]), "=r"(r[3]) : "r"(a));
}
__device__ __forceinline__ void ldsm_x4t(uint32_t r[4], uint32_t a) {
    asm volatile("ldmatrix.sync.aligned.m8n8.x4.trans.shared.b16 {%0,%1,%2,%3}, [%4];"
        : "=r"(r[0]), "=r"(r[1]), "=r"(r[2]), "=r"(r[3]) : "r"(a));
}
__device__ __forceinline__ void mma16816(float c[4], const uint32_t a[4],
                                         uint32_t b0, uint32_t b1) {
    asm volatile("mma.sync.aligned.m16n8k16.row.col.f32.f16.f16.f32 "
        "{%0,%1,%2,%3}, {%4,%5,%6,%7}, {%8,%9}, {%0,%1,%2,%3};"
        : "+f"(c[0]), "+f"(c[1]), "+f"(c[2]), "+f"(c[3])
        : "r"(a[0]), "r"(a[1]), "r"(a[2]), "r"(a[3]), "r"(b0), "r"(b1));
}
__device__ __forceinline__ void mma16816h(uint32_t c[2], const uint32_t a[4],
                                          uint32_t b0, uint32_t b1) {
    asm volatile("mma.sync.aligned.m16n8k16.row.col.f16.f16.f16.f16 "
        "{%0,%1}, {%2,%3,%4,%5}, {%6,%7}, {%0,%1};"
        : "+r"(c[0]), "+r"(c[1])
        : "r"(a[0]), "r"(a[1]), "r"(a[2]), "r"(a[3]), "r"(b0), "r"(b1));
}
__device__ __forceinline__ uint32_t packh2(float lo, float hi) {
    __half2 h = __floats2half2_rn(lo, hi);
    return *reinterpret_cast<uint32_t*>(&h);
}
__device__ __forceinline__ void cp16(void* s, const void* g) {
    asm volatile("cp.async.cg.shared.global [%0], [%1], 16;"
        :: "r"(smem_u32(s)), "l"(g));
}
__device__ __forceinline__ void cp_commit() {
    asm volatile("cp.async.commit_group;");
}
template <int N> __device__ __forceinline__ void cp_wait() {
    asm volatile("cp.async.wait_group %0;" :: "n"(N));
}
__device__ __forceinline__ uint32_t h2ex2(uint32_t x) {
    uint32_t r;
    asm("ex2.approx.f16x2 %0, %1;" : "=r"(r) : "r"(x));
    return r;
}
__device__ __forceinline__ __half2 u2h2(uint32_t x) {
    return *reinterpret_cast<__half2*>(&x);
}

// ---------------------------------------------------------------------------
__global__ void f2h_all(const float* __restrict__ x, const float* __restrict__ wq,
                        const float* __restrict__ wo,
                        __half* __restrict__ xh, __half* __restrict__ wqh,
                        __half* __restrict__ woh)
{
    int i = (blockIdx.x * blockDim.x + threadIdx.x) * 4;
    const float* s; __half* d; float sc = 1.0f; int j;
    if (i < NX)            { s = x;  d = xh;  j = i; }
    else if (i < NX + NQ)  { j = i - NX; s = wq; d = wqh;
                             if (j < HID * DIM) sc = QPRESCALE; }
    else if (i < NX+NQ+NO) { j = i - NX - NQ; s = wo; d = woh; }
    else return;
    float4 v = *(const float4*)(s + j);
    *(uint32_t*)(d + j)     = packh2(v.x * sc, v.y * sc);
    *(uint32_t*)(d + j + 2) = packh2(v.z * sc, v.w * sc);
}

// ---------------------------------------------------------------------------
// fp16 tensor-core GEMM, generalized (BM, BN). BK=64. WN=2 warps along N.
// THREADS = (BM/32)*2*32. 3-buffer cp.async ring; proven ordering:
// wait<1> -> __syncthreads -> compute -> stage(kt+2) -> commit.
// ---------------------------------------------------------------------------
template <int BM, int BN, bool OUT_HALF, bool HAS_BIAS>
__global__ __launch_bounds__((BM / 32) * 64)
void hgemm_kernel(const __half* __restrict__ A, const __half* __restrict__ Bg,
                  void* __restrict__ Cg, const float* __restrict__ bias,
                  int M, int N, int K)
{
    constexpr int THREADS = (BM / 32) * 64;       // (BM/32)*WN warps, WN=2
    constexpr int NSPAN = BN / 2;                 // cols per warp
    constexpr int NT = NSPAN / 8;                 // 8-wide n-tiles per warp
    constexpr int BPITCH = BN + 8;
    constexpr int A_SZ = BM * 72;                 // halfs per A buffer
    constexpr int B_SZ = 64 * BPITCH;             // halfs per B buffer

    const int b = blockIdx.z;
    const __half* Bm = Bg + (size_t)b * K * N;
    const int rowC0 = blockIdx.y * BM;
    const int colC0 = blockIdx.x * BN;

    extern __shared__ __half dsm[];
    __half* As = dsm;                 // [3][BM][72]
    __half* Bs = dsm + 3 * A_SZ;      // [3][64][BPITCH]

    const int tid = threadIdx.x, lane = tid & 31, warp = tid >> 5;
    const int g = lane >> 2, tg = lane & 3;
    const int wm = warp >> 1, wn = warp & 1;

    const int lm_koff = ((lane >> 3) & 1) * 8 + (lane & 7);
    const int lm_noff = wn * NSPAN + ((lane >> 4) & 1) * 8;

    auto stage = [&](int buf, int k0) {
        __half* Ab = As + buf * A_SZ;
        #pragma unroll
        for (int it = 0; it < BM * 8 / THREADS; it++) {
            int c = tid + it * THREADS;
            int m = c >> 3, o8 = (c & 7) * 8;
            cp16(Ab + m * 72 + o8, A + (size_t)(rowC0 + m) * K + k0 + o8);
        }
        __half* Bb = Bs + buf * B_SZ;
        #pragma unroll
        for (int it = 0; it < BN * 8 / THREADS; it++) {
            int c = tid + it * THREADS;
            int kk = c / (BN / 8), n8 = (c % (BN / 8)) * 8;
            cp16(Bb + kk * BPITCH + n8, Bm + (size_t)(k0 + kk) * N + colC0 + n8);
        }
    };

    float acc[2][NT][4] = {};
    const int ntiles = K >> 6;

    stage(0, 0);
    cp_commit();
    if (ntiles > 1) stage(1, 64);
    cp_commit();

    for (int kt = 0; kt < ntiles; kt++) {
        const int cur = kt % 3;
        cp_wait<1>();          // this thread's tile-kt copies complete
        __syncthreads();       // ALL threads' tile-kt copies complete

        const __half* Ab = As + cur * A_SZ;
        const uint32_t bsb = smem_u32(Bs + cur * B_SZ);
        #pragma unroll
        for (int kc = 0; kc < 4; kc++) {
            uint32_t af[2][4];
            #pragma unroll
            for (int mt = 0; mt < 2; mt++) {
                const __half* ap = Ab + (wm * 32 + mt * 16) * 72 + 16 * kc + 2 * tg;
                af[mt][0] = *(const uint32_t*)(ap + g * 72);
                af[mt][1] = *(const uint32_t*)(ap + (g + 8) * 72);
                af[mt][2] = *(const uint32_t*)(ap + g * 72 + 8);
                af[mt][3] = *(const uint32_t*)(ap + (g + 8) * 72 + 8);
            }
            uint32_t bf[NT][2];
            #pragma unroll
            for (int ntp = 0; ntp < NT / 2; ntp++) {
                uint32_t r[4];
                uint32_t a = bsb + 2 * ((16 * kc + lm_koff) * BPITCH +
                                        lm_noff + 16 * ntp);
                ldsm_x4t(r, a);
                bf[2*ntp][0] = r[0]; bf[2*ntp][1] = r[1];
                bf[2*ntp+1][0] = r[2]; bf[2*ntp+1][1] = r[3];
            }
            #pragma unroll
            for (int nt = 0; nt < NT; nt++)
                #pragma unroll
                for (int mt = 0; mt < 2; mt++)
                    mma16816(acc[mt][nt], af[mt], bf[nt][0], bf[nt][1]);
        }

        if (kt + 2 < ntiles) stage((kt + 2) % 3, (kt + 2) * 64);
        cp_commit();
    }

    #pragma unroll
    for (int mt = 0; mt < 2; mt++) {
        int m0 = rowC0 + wm * 32 + mt * 16 + g;
        #pragma unroll
        for (int nt = 0; nt < NT; nt++) {
            int n = colC0 + wn * NSPAN + nt * 8 + 2 * tg;
            float c0 = acc[mt][nt][0], c1 = acc[mt][nt][1];
            float c2 = acc[mt][nt][2], c3 = acc[mt][nt][3];
            if (OUT_HALF) {
                __half* Ch = (__half*)Cg + (size_t)b * M * N;
                *(uint32_t*)(Ch + (size_t)m0 * N + n)       = packh2(c0, c1);
                *(uint32_t*)(Ch + (size_t)(m0 + 8) * N + n) = packh2(c2, c3);
            } else {
                float* Cf = (float*)Cg + (size_t)b * M * N;
                float bv0 = HAS_BIAS ? bias[m0] : 0.0f;
                float bv1 = HAS_BIAS ? bias[m0 + 8] : 0.0f;
                *(float2*)(Cf + (size_t)m0 * N + n)       = make_float2(c0 + bv0, c1 + bv0);
                *(float2*)(Cf + (size_t)(m0 + 8) * N + n) = make_float2(c2 + bv1, c3 + bv1);
            }
        }
    }
}

// ---------------------------------------------------------------------------
// fp16 flash attention — exact R12 version (proven at 139.7us / 6.95e-4).
// 4 warps x 32 q-rows, pipelined across KV tiles (S(t+1) with exp/PV(t)).
// K triple-buffered, V quad-buffered (V2,V3 alias dead Q staging).
// ---------------------------------------------------------------------------
#define NTILES 32
#define KVB 9216                      // bytes per K or V buffer (64 x 72 halfs)
#define KS_OFF 18432                  // 3 K buffers
#define V01_OFF (18432 + 3 * KVB)     // 46080: V buffers 0,1
#define FL_BYTES (V01_OFF + 2 * KVB)  // 64512

__global__ __launch_bounds__(128)
void flash_kernel(const __half* __restrict__ qkv, __half* __restrict__ ao)
{
    const int b = blockIdx.z, h = blockIdx.y;
    const int i0 = blockIdx.x * 128;
    const int tid = threadIdx.x, lane = tid & 31, warp = tid >> 5;
    const int g = lane >> 2, tg = lane & 3;

    const __half* qg = qkv + ((size_t)b * QKV_ROWS + h * DHEAD) * LL;
    const __half* kg = qkv + ((size_t)b * QKV_ROWS + HID + h * DHEAD) * LL;
    const __half* vg = qkv + ((size_t)b * QKV_ROWS + 2 * HID + h * DHEAD) * LL;

    extern __shared__ __half sm[];
    __half* QV = sm;                          // Q staging / V2,V3 / O transpose
    const uint32_t sb = smem_u32(sm);

    auto stageK = [&](int buf, int j0) {
        __half* Kb = (__half*)((char*)sm + KS_OFF + buf * KVB);
        #pragma unroll
        for (int it = 0; it < 4; it++) {
            int idx = tid + it * 128;
            int d = idx >> 3, c8 = (idx & 7) * 8;
            cp16(Kb + d * 72 + c8, kg + (size_t)d * LL + j0 + c8);
        }
    };
    auto stageV = [&](int buf, int j0) {
        __half* Vb = (__half*)((char*)sm +
                     ((buf & 2) ? (buf & 1) * KVB : V01_OFF + (buf & 1) * KVB));
        #pragma unroll
        for (int it = 0; it < 4; it++) {
            int idx = tid + it * 128;
            int d = idx >> 3, c8 = (idx & 7) * 8;
            cp16(Vb + d * 72 + c8, vg + (size_t)d * LL + j0 + c8);
        }
    };

    // Prologue: G0, G1 in flight (V0,V1 to non-aliased region)
    stageK(0, 0);    stageV(0, 0);    cp_commit();
    stageK(1, 64);   stageV(1, 64);   cp_commit();

    // Stage Q (d, r) pitch 136; region is dead after fragments are built
    #pragma unroll
    for (int it = 0; it < 8; it++) {
        int idx = tid + it * 128;
        int d = idx >> 4, q8 = (idx & 15) * 8;
        *(uint4*)(QV + d * 136 + q8) = *(const uint4*)(qg + (size_t)d * LL + i0 + q8);
    }
    __syncthreads();

    uint32_t qa[2][4][4];
    {
        int row = lane & 7;
        int c_off = ((lane >> 3) & 1) * 8;
        int d_off = ((lane >> 4) & 1) * 8;
        #pragma unroll
        for (int mt = 0; mt < 2; mt++)
            #pragma unroll
            for (int kc = 0; kc < 4; kc++) {
                uint32_t a = sb + 2 * ((16 * kc + d_off + row) * 136 +
                                       warp * 32 + mt * 16 + c_off);
                ldsm_x4t(qa[mt][kc], a);
            }
    }

    cp_wait<1>();        // own G0 done
    __syncthreads();     // all threads' G0 done; all qa ldsm complete

    const int lmr = lane & 7;
    const int lmo1 = ((lane >> 3) & 1) * 8;
    const int lmo2 = ((lane >> 4) & 1) * 8;

    float oc[2][8][4] = {};
    float lr[2][2] = {};
    uint32_t schA[2][8][2], schB[2][8][2];

    // S(0) from K buffer 0
    {
        #pragma unroll
        for (int mt = 0; mt < 2; mt++)
            #pragma unroll
            for (int jc = 0; jc < 8; jc++) { schA[mt][jc][0] = 0; schA[mt][jc][1] = 0; }
        const uint32_t kbb = sb + KS_OFF;
        #pragma unroll
        for (int kc = 0; kc < 4; kc++) {
            uint32_t kb[8][2];
            #pragma unroll
            for (int jp = 0; jp < 4; jp++) {
                uint32_t r[4];
                uint32_t a = kbb + 2 * ((16 * kc + lmo1 + lmr) * 72 + 16 * jp + lmo2);
                ldsm_x4t(r, a);
                kb[2*jp][0] = r[0]; kb[2*jp][1] = r[1];
                kb[2*jp+1][0] = r[2]; kb[2*jp+1][1] = r[3];
            }
            #pragma unroll
            for (int jc = 0; jc < 8; jc++)
                #pragma unroll
                for (int mt = 0; mt < 2; mt++)
                    mma16816h(schA[mt][jc], qa[mt][kc], kb[jc][0], kb[jc][1]);
        }
    }

    auto body = [&](uint32_t (&si)[2][8][2], uint32_t (&so)[2][8][2], int t) {
        if (t + 2 < NTILES) { stageK((t + 2) % 3, (t + 2) * 64);
                              stageV((t + 2) & 3, (t + 2) * 64); }
        cp_commit();
        cp_wait<1>();
        __syncthreads();

        const bool doS = (t + 1 < NTILES);
        const uint32_t kbb = sb + KS_OFF + ((t + 1) % 3) * KVB;
        const uint32_t vbb = sb + ((t & 2) ? (t & 1) * KVB
                                           : V01_OFF + (t & 1) * KVB);
        if (doS) {
            #pragma unroll
            for (int mt = 0; mt < 2; mt++)
                #pragma unroll
                for (int jc = 0; jc < 8; jc++) { so[mt][jc][0] = 0; so[mt][jc][1] = 0; }
        }

        __half2 hl[2][2] = {{__half2(0,0), __half2(0,0)},
                            {__half2(0,0), __half2(0,0)}};
        #pragma unroll
        for (int blk = 0; blk < 4; blk++) {
            if (doS) {
                uint32_t kb[8][2];
                #pragma unroll
                for (int jp = 0; jp < 4; jp++) {
                    uint32_t r[4];
                    uint32_t a = kbb + 2 * ((16 * blk + lmo1 + lmr) * 72 +
                                            16 * jp + lmo2);
                    ldsm_x4t(r, a);
                    kb[2*jp][0] = r[0]; kb[2*jp][1] = r[1];
                    kb[2*jp+1][0] = r[2]; kb[2*jp+1][1] = r[3];
                }
                #pragma unroll
                for (int jc = 0; jc < 8; jc++)
                    #pragma unroll
                    for (int mt = 0; mt < 2; mt++)
                        mma16816h(so[mt][jc], qa[mt][blk], kb[jc][0], kb[jc][1]);
            }
            uint32_t pa[2][4];
            #pragma unroll
            for (int mt = 0; mt < 2; mt++) {
                pa[mt][0] = h2ex2(si[mt][2*blk][0]);
                pa[mt][1] = h2ex2(si[mt][2*blk][1]);
                pa[mt][2] = h2ex2(si[mt][2*blk+1][0]);
                pa[mt][3] = h2ex2(si[mt][2*blk+1][1]);
                hl[mt][0] = __hadd2(hl[mt][0], __hadd2(u2h2(pa[mt][0]), u2h2(pa[mt][2])));
                hl[mt][1] = __hadd2(hl[mt][1], __hadd2(u2h2(pa[mt][1]), u2h2(pa[mt][3])));
            }
            #pragma unroll
            for (int dp = 0; dp < 4; dp++) {
                uint32_t r[4];
                uint32_t a = vbb + 2 * ((16 * dp + lmo2 + lmr) * 72 +
                                        16 * blk + lmo1);
                ldsm_x4(r, a);
                #pragma unroll
                for (int mt = 0; mt < 2; mt++) {
                    mma16816(oc[mt][2*dp],   pa[mt], r[0], r[1]);
                    mma16816(oc[mt][2*dp+1], pa[mt], r[2], r[3]);
                }
            }
        }
        #pragma unroll
        for (int mt = 0; mt < 2; mt++) {
            float2 f0 = __half22float2(hl[mt][0]);
            float2 f1 = __half22float2(hl[mt][1]);
            lr[mt][0] += f0.x + f0.y;
            lr[mt][1] += f1.x + f1.y;
        }
    };

    for (int jt = 0; jt < NTILES; jt += 2) {
        body(schA, schB, jt);
        body(schB, schA, jt + 1);
    }

    #pragma unroll
    for (int mt = 0; mt < 2; mt++)
        #pragma unroll
        for (int rr = 0; rr < 2; rr++) {
            lr[mt][rr] += __shfl_xor_sync(~0u, lr[mt][rr], 1);
            lr[mt][rr] += __shfl_xor_sync(~0u, lr[mt][rr], 2);
        }

    __syncthreads();   // all PV ldsm done before QV reuse for O

    #pragma unroll
    for (int mt = 0; mt < 2; mt++) {
        float inv0 = 1.0f / lr[mt][0];
        float inv1 = 1.0f / lr[mt][1];
        int r_lo = warp * 32 + mt * 16 + g, r_hi = r_lo + 8;
        #pragma unroll
        for (int dc = 0; dc < 8; dc++) {
            int d = dc * 8 + 2 * tg;
            QV[d * 136 + r_lo]       = __float2half(oc[mt][dc][0] * inv0);
            QV[(d + 1) * 136 + r_lo] = __float2half(oc[mt][dc][1] * inv0);
            QV[d * 136 + r_hi]       = __float2half(oc[mt][dc][2] * inv1);
            QV[(d + 1) * 136 + r_hi] = __float2half(oc[mt][dc][3] * inv1);
        }
    }
    __syncthreads();

    __half* aog = ao + ((size_t)b * HID + h * DHEAD) * LL;
    #pragma unroll
    for (int it = 0; it < 8; it++) {
        int idx = tid + it * 128;
        int d = idx >> 4, q8 = (idx & 15) * 8;
        *(uint4*)(aog + (size_t)d * LL + i0 + q8) = *(const uint4*)(QV + d * 136 + q8);
    }
}

// ---------------------------------------------------------------------------
extern "C" void kernel_launch(void* const* d_in, const int* in_sizes, int n_in,
                              void* d_out, int out_size)
{
    (void)in_sizes; (void)n_in; (void)out_size;
    const float* x     = (const float*)d_in[0];
    const float* w_qkv = (const float*)d_in[1];
    const float* w_out = (const float*)d_in[2];
    const float* b_out = (const float*)d_in[3];
    float* out = (float*)d_out;

    __half *qkv, *ao, *xh, *wqk, *wo;
    cudaGetSymbolAddress((void**)&qkv, g_qkv);
    cudaGetSymbolAddress((void**)&ao,  g_ao);
    cudaGetSymbolAddress((void**)&xh,  g_xh);
    cudaGetSymbolAddress((void**)&wqk, g_wqk);
    cudaGetSymbolAddress((void**)&wo,  g_wo);

    {
        int total4 = (NX + NQ + NO) / 4;
        f2h_all<<<(total4 + 255) / 256, 256>>>(x, w_qkv, w_out, xh, wqk, wo);
    }

    const int gm1_smem = 3 * (128 * 72 + 64 * 136) * 2;   // 107520
    const int gm3_smem = 3 * (64 * 72 + 64 * 72) * 2;     // 55296
    cudaFuncSetAttribute((const void*)hgemm_kernel<128, 128, true, false>,
                         cudaFuncAttributeMaxDynamicSharedMemorySize, gm1_smem);
    cudaFuncSetAttribute((const void*)hgemm_kernel<64, 64, false, true>,
                         cudaFuncAttributeMaxDynamicSharedMemorySize, gm3_smem);
    cudaFuncSetAttribute((const void*)flash_kernel,
                         cudaFuncAttributeMaxDynamicSharedMemorySize, FL_BYTES);

    // 1) QKV projection (8 warps, BM=BN=128)
    dim3 g1(LL / 128, QKV_ROWS / 128, BATCH);
    hgemm_kernel<128, 128, true, false><<<g1, 256, gm1_smem>>>(
        wqk, xh, qkv, nullptr, QKV_ROWS, LL, DIM);

    // 2) Flash attention (exact R12)
    dim3 g2(LL / 128, HEADS, BATCH);
    flash_kernel<<<g2, 128, FL_BYTES>>>(qkv, ao);

    // 3) Output projection + bias (4 warps, BM=BN=64, 512 CTAs, 4 CTAs/SM)
    dim3 g3(LL / 64, DIM / 64, BATCH);
    hgemm_kernel<64, 64, false, true><<<g3, 128, gm3_smem>>>(
        wo, ao, out, b_out, DIM, LL, HID);
}